// round 16
// baseline (speedup 1.0000x reference)
#include <cuda_runtime.h>
#include <cuda_fp16.h>
#include <cstdint>
#include <math.h>

#define TOKENS 32768
#define EDIM   512
#define FFN    2048
#define NQ     8

// ---------------- scratch (device globals: allowed) ----------------
__device__ __half g_W2h[EDIM * FFN];           // 2 MB
__device__ __half g_Hh[(size_t)TOKENS * FFN];  // 128 MB

// ---------------- prep: W2 -> fp16 ----------------
__global__ void __launch_bounds__(256) prep_kernel(const float* __restrict__ W2) {
    int i = (blockIdx.x * blockDim.x + threadIdx.x) * 4;
    float4 v = *reinterpret_cast<const float4*>(W2 + i);
    __half2* dst = reinterpret_cast<__half2*>(g_W2h + i);
    dst[0] = __floats2half2_rn(v.x, v.y);
    dst[1] = __floats2half2_rn(v.z, v.w);
}

// ---------------- h kernel: 512 thr, 4 outputs/thread, 32 tokens/block ----------------
// w[4][8] = 32 regs (vs 64 in R15) + launch_bounds(512,2) -> 2 blocks/SM = 32 warps.
__global__ void __launch_bounds__(512, 2)
h_kernel(const float* __restrict__ x, const float* __restrict__ theta,
         const float* __restrict__ W1, const float* __restrict__ b1)
{
    __shared__ float qv[32][8];
    const int tid = threadIdx.x;
    const int m0  = blockIdx.x * 32;

    if (tid < 256) {
        int m = tid >> 3, q = tid & 7;
        qv[m][q] = cosf(x[(size_t)(m0 + m) * EDIM + q]) * cosf(theta[q]);
    }
    __syncthreads();

    const int f0 = tid * 4;
    float w[4][8];
    #pragma unroll
    for (int i = 0; i < 4; i++) {
        const float4* p = reinterpret_cast<const float4*>(W1 + (size_t)(f0 + i) * NQ);
        float4 a = p[0], b = p[1];
        w[i][0] = a.x; w[i][1] = a.y; w[i][2] = a.z; w[i][3] = a.w;
        w[i][4] = b.x; w[i][5] = b.y; w[i][6] = b.z; w[i][7] = b.w;
    }
    float bb[4];
    {
        const float4* p = reinterpret_cast<const float4*>(b1 + f0);
        float4 a = p[0];
        bb[0] = a.x; bb[1] = a.y; bb[2] = a.z; bb[3] = a.w;
    }

    #pragma unroll 1
    for (int m = 0; m < 32; m++) {
        const float4* qp = reinterpret_cast<const float4*>(qv[m]);   // warp-uniform -> broadcast
        float4 qA = qp[0], qB = qp[1];
        float acc[4];
        #pragma unroll
        for (int i = 0; i < 4; i++) {
            float s = bb[i];
            s += qA.x * w[i][0]; s += qA.y * w[i][1];
            s += qA.z * w[i][2]; s += qA.w * w[i][3];
            s += qB.x * w[i][4]; s += qB.y * w[i][5];
            s += qB.z * w[i][6]; s += qB.w * w[i][7];
            acc[i] = fmaxf(s, 0.0f);
        }
        uint32_t p0, p1;
        asm("cvt.rn.f16x2.f32 %0, %1, %2;" : "=r"(p0) : "f"(acc[1]), "f"(acc[0]));
        asm("cvt.rn.f16x2.f32 %0, %1, %2;" : "=r"(p1) : "f"(acc[3]), "f"(acc[2]));
        __half* dst = g_Hh + (size_t)(m0 + m) * FFN + f0;
        asm volatile("st.global.v2.b32 [%0], {%1,%2};"
                     :: "l"(dst), "r"(p0), "r"(p1) : "memory");
    }
}

// ---------------- GEMM: out = H @ W2^T + b2 (unchanged proven core) ----------------
#define BM 128
#define BN 128
#define BK 64
#define GT 256
#define STAGES 3
#define CHUNKS (FFN / BK)   // 32
#define STAGE_BYTES 32768
#define SMEM_TOTAL (STAGES * STAGE_BYTES)   // 96 KB

__device__ __forceinline__ uint32_t s2u(const void* p) {
    uint32_t a;
    asm("{ .reg .u64 t; cvta.to.shared.u64 t, %1; cvt.u32.u64 %0, t; }" : "=r"(a) : "l"(p));
    return a;
}
#define LDSM_X4(r, addr) \
    asm volatile("ldmatrix.sync.aligned.m8n8.x4.shared.b16 {%0,%1,%2,%3}, [%4];" \
        : "=r"((r)[0]), "=r"((r)[1]), "=r"((r)[2]), "=r"((r)[3]) : "r"(addr))

__device__ __forceinline__ void mma_f16(float* d, const uint32_t* a, uint32_t b0, uint32_t b1) {
    asm volatile(
        "mma.sync.aligned.m16n8k16.row.col.f32.f16.f16.f32 "
        "{%0,%1,%2,%3}, {%4,%5,%6,%7}, {%8,%9}, {%0,%1,%2,%3};"
        : "+f"(d[0]), "+f"(d[1]), "+f"(d[2]), "+f"(d[3])
        : "r"(a[0]), "r"(a[1]), "r"(a[2]), "r"(a[3]), "r"(b0), "r"(b1));
}

__global__ void __launch_bounds__(GT, 2)
gemm_kernel(const float* __restrict__ b2, float* __restrict__ out)
{
    extern __shared__ unsigned char smem[];
    const uint32_t sb = s2u(smem);
    const int tid  = threadIdx.x;
    const int warp = tid >> 5;
    const int lane = tid & 31;
    const int g  = lane >> 2;
    const int tg = lane & 3;

    const int m0 = blockIdx.x * BM;
    const int n0 = blockIdx.y * BN;

    const int wm = (warp >> 2) * 64;
    const int wn = (warp & 3) * 32;

    const int ar  = (lane & 7) + ((lane >> 3) & 1) * 8;
    const int ac8 = ((lane >> 4) & 1) * 8;
    const int br  = (lane & 7) + ((lane >> 4) & 1) * 8;
    const int bc8 = ((lane >> 3) & 1) * 8;

    float acc[4][4][4];
    #pragma unroll
    for (int mi = 0; mi < 4; mi++)
        #pragma unroll
        for (int ni = 0; ni < 4; ni++)
            #pragma unroll
            for (int r = 0; r < 4; r++)
                acc[mi][ni][r] = 0.0f;

    auto produce = [&](int c, int slot) {
        const uint32_t aB = sb + slot * STAGE_BYTES;
        const uint32_t bB = aB + 16384;
        #pragma unroll
        for (int i = 0; i < 8; i++) {
            int idx = tid + i * GT;
            int row = (idx >> 3) & 127;
            int kq  = idx & 7;
            uint32_t off = (uint32_t)row * 128 + (((uint32_t)kq * 16) ^ ((row & 7) << 4));
            if (idx < 1024) {
                const __half* src = g_Hh + (size_t)(m0 + row) * FFN + c * BK + kq * 8;
                asm volatile("cp.async.cg.shared.global [%0], [%1], 16;"
                             :: "r"(aB + off), "l"(src) : "memory");
            } else {
                const __half* src = g_W2h + (size_t)(n0 + row) * FFN + c * BK + kq * 8;
                asm volatile("cp.async.cg.shared.global [%0], [%1], 16;"
                             :: "r"(bB + off), "l"(src) : "memory");
            }
        }
        asm volatile("cp.async.commit_group;" ::: "memory");
    };

    auto consume = [&](int slot) {
        const uint32_t aB = sb + slot * STAGE_BYTES;
        const uint32_t bB = aB + 16384;
        #pragma unroll
        for (int ks = 0; ks < 4; ks++) {
            int kb = ks * 16;
            uint32_t afr[4][4];
            #pragma unroll
            for (int mi = 0; mi < 4; mi++) {
                int r = wm + mi * 16 + ar;
                uint32_t cb = (uint32_t)(kb + ac8) * 2;
                LDSM_X4(afr[mi], aB + (uint32_t)r * 128 + (cb ^ ((r & 7) << 4)));
            }
            uint32_t bfr[2][4];
            #pragma unroll
            for (int p = 0; p < 2; p++) {
                int n = wn + p * 16 + br;
                uint32_t cb = (uint32_t)(kb + bc8) * 2;
                LDSM_X4(bfr[p], bB + (uint32_t)n * 128 + (cb ^ ((n & 7) << 4)));
            }
            #pragma unroll
            for (int ni = 0; ni < 4; ni++) {
                uint32_t b0 = bfr[ni >> 1][(ni & 1) * 2 + 0];
                uint32_t b1 = bfr[ni >> 1][(ni & 1) * 2 + 1];
                #pragma unroll
                for (int mi = 0; mi < 4; mi++)
                    mma_f16(acc[mi][ni], afr[mi], b0, b1);
            }
        }
    };

    produce(0, 0);
    produce(1, 1);

    #pragma unroll 1
    for (int c = 0; c < CHUNKS - 1; c++) {
        asm volatile("cp.async.wait_group 1;" ::: "memory");
        __syncthreads();
        consume(c % STAGES);
        if (c + 2 < CHUNKS) produce(c + 2, (c + 2) % STAGES);
    }
    asm volatile("cp.async.wait_group 0;" ::: "memory");
    __syncthreads();
    consume((CHUNKS - 1) % STAGES);

    #pragma unroll
    for (int mi = 0; mi < 4; mi++) {
        #pragma unroll
        for (int ni = 0; ni < 4; ni++) {
            int row = m0 + wm + mi * 16 + g;
            int col = n0 + wn + ni * 8 + 2 * tg;
            float b2a = b2[col];
            float b2b = b2[col + 1];
            float2 v0 = make_float2(acc[mi][ni][0] + b2a, acc[mi][ni][1] + b2b);
            float2 v1 = make_float2(acc[mi][ni][2] + b2a, acc[mi][ni][3] + b2b);
            *reinterpret_cast<float2*>(out + (size_t)row * EDIM + col)       = v0;
            *reinterpret_cast<float2*>(out + (size_t)(row + 8) * EDIM + col) = v1;
        }
    }
}

extern "C" void kernel_launch(void* const* d_in, const int* in_sizes, int n_in,
                              void* d_out, int out_size) {
    const float* x     = (const float*)d_in[0];
    const float* theta = (const float*)d_in[1];
    const float* W1    = (const float*)d_in[2];
    const float* b1    = (const float*)d_in[3];
    const float* W2    = (const float*)d_in[4];
    const float* b2    = (const float*)d_in[5];
    float* out = (float*)d_out;

    cudaFuncSetAttribute(gemm_kernel,
                         cudaFuncAttributeMaxDynamicSharedMemorySize, SMEM_TOTAL);

    dim3 ggrid(TOKENS / BM, EDIM / BN);   // (256, 4) full grid

    // DAG: s2: prep ; main: h ; gemm on main waits for prep (event) + h (stream order).
    cudaStream_t s2 = nullptr;
    cudaEvent_t eFork = nullptr, ePrep = nullptr;
    bool ok = (cudaStreamCreateWithFlags(&s2, cudaStreamNonBlocking) == cudaSuccess)
           && (cudaEventCreateWithFlags(&eFork, cudaEventDisableTiming) == cudaSuccess)
           && (cudaEventCreateWithFlags(&ePrep, cudaEventDisableTiming) == cudaSuccess);

    if (ok) {
        cudaEventRecord(eFork, 0);
        cudaStreamWaitEvent(s2, eFork, 0);
        prep_kernel<<<(EDIM * FFN / 4) / 256, 256, 0, s2>>>(W2);   // s2 (|| h)
        cudaEventRecord(ePrep, s2);

        h_kernel<<<TOKENS / 32, 512>>>(x, theta, W1, b1);          // main

        cudaStreamWaitEvent(0, ePrep, 0);
        gemm_kernel<<<ggrid, GT, SMEM_TOTAL>>>(b2, out);           // main
    } else {
        prep_kernel<<<(EDIM * FFN / 4) / 256, 256>>>(W2);
        h_kernel<<<TOKENS / 32, 512>>>(x, theta, W1, b1);
        gemm_kernel<<<ggrid, GT, SMEM_TOTAL>>>(b2, out);
    }
}

// round 17
// speedup vs baseline: 1.0020x; 1.0020x over previous
#include <cuda_runtime.h>
#include <cuda_fp16.h>
#include <cstdint>
#include <math.h>

#define TOKENS 32768
#define EDIM   512
#define FFN    2048
#define NQ     8

// ---------------- scratch (device globals: allowed) ----------------
__device__ __half g_W2h[EDIM * FFN];           // 2 MB
__device__ __half g_Hh[(size_t)TOKENS * FFN];  // 128 MB

// ---------------- prep: W2 -> fp16 ----------------
__global__ void __launch_bounds__(256) prep_kernel(const float* __restrict__ W2) {
    int i = (blockIdx.x * blockDim.x + threadIdx.x) * 4;
    float4 v = *reinterpret_cast<const float4*>(W2 + i);
    __half2* dst = reinterpret_cast<__half2*>(g_W2h + i);
    dst[0] = __floats2half2_rn(v.x, v.y);
    dst[1] = __floats2half2_rn(v.z, v.w);
}

// ---------------- h kernel (R12 proven version, verbatim) ----------------
__global__ void __launch_bounds__(256)
h_kernel(const float* __restrict__ x, const float* __restrict__ theta,
         const float* __restrict__ W1, const float* __restrict__ b1)
{
    __shared__ float qv[32][8];
    const int tid = threadIdx.x;
    const int m0  = blockIdx.x * 32;

    {
        int m = tid >> 3, q = tid & 7;
        qv[m][q] = cosf(x[(size_t)(m0 + m) * EDIM + q]) * cosf(theta[q]);
    }
    __syncthreads();

    const int f0 = tid * 8;
    float w[8][8];
    #pragma unroll
    for (int i = 0; i < 8; i++) {
        const float4* p = reinterpret_cast<const float4*>(W1 + (size_t)(f0 + i) * NQ);
        float4 a = p[0], b = p[1];
        w[i][0] = a.x; w[i][1] = a.y; w[i][2] = a.z; w[i][3] = a.w;
        w[i][4] = b.x; w[i][5] = b.y; w[i][6] = b.z; w[i][7] = b.w;
    }
    float bb[8];
    {
        const float4* p = reinterpret_cast<const float4*>(b1 + f0);
        float4 a = p[0], b = p[1];
        bb[0] = a.x; bb[1] = a.y; bb[2] = a.z; bb[3] = a.w;
        bb[4] = b.x; bb[5] = b.y; bb[6] = b.z; bb[7] = b.w;
    }

    for (int m = 0; m < 32; m++) {
        float q0 = qv[m][0], q1 = qv[m][1], q2 = qv[m][2], q3 = qv[m][3];
        float q4 = qv[m][4], q5 = qv[m][5], q6 = qv[m][6], q7 = qv[m][7];
        float acc[8];
        #pragma unroll
        for (int i = 0; i < 8; i++) {
            float s = bb[i];
            s += q0 * w[i][0]; s += q1 * w[i][1];
            s += q2 * w[i][2]; s += q3 * w[i][3];
            s += q4 * w[i][4]; s += q5 * w[i][5];
            s += q6 * w[i][6]; s += q7 * w[i][7];
            acc[i] = fmaxf(s, 0.0f);
        }
        uint32_t p[4];
        #pragma unroll
        for (int i = 0; i < 4; i++)
            asm("cvt.rn.f16x2.f32 %0, %1, %2;" : "=r"(p[i])
                : "f"(acc[2 * i + 1]), "f"(acc[2 * i]));   // lo = even index
        __half* dst = g_Hh + (size_t)(m0 + m) * FFN + f0;
        asm volatile("st.global.v4.b32 [%0], {%1,%2,%3,%4};"
                     :: "l"(dst), "r"(p[0]), "r"(p[1]), "r"(p[2]), "r"(p[3]) : "memory");
    }
}

// ---------------- GEMM: out = H @ W2^T + b2 (R12 proven core, verbatim) ----------------
#define BM 128
#define BN 128
#define BK 64
#define GT 256
#define STAGES 3
#define CHUNKS (FFN / BK)   // 32
#define STAGE_BYTES 32768
#define SMEM_TOTAL (STAGES * STAGE_BYTES)   // 96 KB

__device__ __forceinline__ uint32_t s2u(const void* p) {
    uint32_t a;
    asm("{ .reg .u64 t; cvta.to.shared.u64 t, %1; cvt.u32.u64 %0, t; }" : "=r"(a) : "l"(p));
    return a;
}
#define LDSM_X4(r, addr) \
    asm volatile("ldmatrix.sync.aligned.m8n8.x4.shared.b16 {%0,%1,%2,%3}, [%4];" \
        : "=r"((r)[0]), "=r"((r)[1]), "=r"((r)[2]), "=r"((r)[3]) : "r"(addr))

__device__ __forceinline__ void mma_f16(float* d, const uint32_t* a, uint32_t b0, uint32_t b1) {
    asm volatile(
        "mma.sync.aligned.m16n8k16.row.col.f32.f16.f16.f32 "
        "{%0,%1,%2,%3}, {%4,%5,%6,%7}, {%8,%9}, {%0,%1,%2,%3};"
        : "+f"(d[0]), "+f"(d[1]), "+f"(d[2]), "+f"(d[3])
        : "r"(a[0]), "r"(a[1]), "r"(a[2]), "r"(a[3]), "r"(b0), "r"(b1));
}

__global__ void __launch_bounds__(GT, 2)
gemm_kernel(const float* __restrict__ b2, float* __restrict__ out)
{
    extern __shared__ unsigned char smem[];
    const uint32_t sb = s2u(smem);
    const int tid  = threadIdx.x;
    const int warp = tid >> 5;
    const int lane = tid & 31;
    const int g  = lane >> 2;
    const int tg = lane & 3;

    const int m0 = blockIdx.x * BM;
    const int n0 = blockIdx.y * BN;

    const int wm = (warp >> 2) * 64;
    const int wn = (warp & 3) * 32;

    const int ar  = (lane & 7) + ((lane >> 3) & 1) * 8;
    const int ac8 = ((lane >> 4) & 1) * 8;
    const int br  = (lane & 7) + ((lane >> 4) & 1) * 8;
    const int bc8 = ((lane >> 3) & 1) * 8;

    float acc[4][4][4];
    #pragma unroll
    for (int mi = 0; mi < 4; mi++)
        #pragma unroll
        for (int ni = 0; ni < 4; ni++)
            #pragma unroll
            for (int r = 0; r < 4; r++)
                acc[mi][ni][r] = 0.0f;

    auto produce = [&](int c, int slot) {
        const uint32_t aB = sb + slot * STAGE_BYTES;
        const uint32_t bB = aB + 16384;
        #pragma unroll
        for (int i = 0; i < 8; i++) {
            int idx = tid + i * GT;
            int row = (idx >> 3) & 127;
            int kq  = idx & 7;
            uint32_t off = (uint32_t)row * 128 + (((uint32_t)kq * 16) ^ ((row & 7) << 4));
            if (idx < 1024) {
                const __half* src = g_Hh + (size_t)(m0 + row) * FFN + c * BK + kq * 8;
                asm volatile("cp.async.cg.shared.global [%0], [%1], 16;"
                             :: "r"(aB + off), "l"(src) : "memory");
            } else {
                const __half* src = g_W2h + (size_t)(n0 + row) * FFN + c * BK + kq * 8;
                asm volatile("cp.async.cg.shared.global [%0], [%1], 16;"
                             :: "r"(bB + off), "l"(src) : "memory");
            }
        }
        asm volatile("cp.async.commit_group;" ::: "memory");
    };

    auto consume = [&](int slot) {
        const uint32_t aB = sb + slot * STAGE_BYTES;
        const uint32_t bB = aB + 16384;
        #pragma unroll
        for (int ks = 0; ks < 4; ks++) {
            int kb = ks * 16;
            uint32_t afr[4][4];
            #pragma unroll
            for (int mi = 0; mi < 4; mi++) {
                int r = wm + mi * 16 + ar;
                uint32_t cb = (uint32_t)(kb + ac8) * 2;
                LDSM_X4(afr[mi], aB + (uint32_t)r * 128 + (cb ^ ((r & 7) << 4)));
            }
            uint32_t bfr[2][4];
            #pragma unroll
            for (int p = 0; p < 2; p++) {
                int n = wn + p * 16 + br;
                uint32_t cb = (uint32_t)(kb + bc8) * 2;
                LDSM_X4(bfr[p], bB + (uint32_t)n * 128 + (cb ^ ((n & 7) << 4)));
            }
            #pragma unroll
            for (int ni = 0; ni < 4; ni++) {
                uint32_t b0 = bfr[ni >> 1][(ni & 1) * 2 + 0];
                uint32_t b1 = bfr[ni >> 1][(ni & 1) * 2 + 1];
                #pragma unroll
                for (int mi = 0; mi < 4; mi++)
                    mma_f16(acc[mi][ni], afr[mi], b0, b1);
            }
        }
    };

    produce(0, 0);
    produce(1, 1);

    #pragma unroll 1
    for (int c = 0; c < CHUNKS - 1; c++) {
        asm volatile("cp.async.wait_group 1;" ::: "memory");
        __syncthreads();
        consume(c % STAGES);
        if (c + 2 < CHUNKS) produce(c + 2, (c + 2) % STAGES);
    }
    asm volatile("cp.async.wait_group 0;" ::: "memory");
    __syncthreads();
    consume((CHUNKS - 1) % STAGES);

    #pragma unroll
    for (int mi = 0; mi < 4; mi++) {
        #pragma unroll
        for (int ni = 0; ni < 4; ni++) {
            int row = m0 + wm + mi * 16 + g;
            int col = n0 + wn + ni * 8 + 2 * tg;
            float b2a = b2[col];
            float b2b = b2[col + 1];
            float2 v0 = make_float2(acc[mi][ni][0] + b2a, acc[mi][ni][1] + b2b);
            float2 v1 = make_float2(acc[mi][ni][2] + b2a, acc[mi][ni][3] + b2b);
            *reinterpret_cast<float2*>(out + (size_t)row * EDIM + col)       = v0;
            *reinterpret_cast<float2*>(out + (size_t)(row + 8) * EDIM + col) = v1;
        }
    }
}

extern "C" void kernel_launch(void* const* d_in, const int* in_sizes, int n_in,
                              void* d_out, int out_size) {
    const float* x     = (const float*)d_in[0];
    const float* theta = (const float*)d_in[1];
    const float* W1    = (const float*)d_in[2];
    const float* b1    = (const float*)d_in[3];
    const float* W2    = (const float*)d_in[4];
    const float* b2    = (const float*)d_in[5];
    float* out = (float*)d_out;

    cudaFuncSetAttribute(gemm_kernel,
                         cudaFuncAttributeMaxDynamicSharedMemorySize, SMEM_TOTAL);

    dim3 ggrid(TOKENS / BM, EDIM / BN);   // (256, 4) full grid

    // Single change vs R12: prep runs on a side stream concurrently with h.
    // gemm (main stream) waits on prep via event; h ordering is stream order.
    cudaStream_t s2 = nullptr;
    cudaEvent_t eFork = nullptr, ePrep = nullptr;
    bool ok = (cudaStreamCreateWithFlags(&s2, cudaStreamNonBlocking) == cudaSuccess)
           && (cudaEventCreateWithFlags(&eFork, cudaEventDisableTiming) == cudaSuccess)
           && (cudaEventCreateWithFlags(&ePrep, cudaEventDisableTiming) == cudaSuccess);

    if (ok) {
        cudaEventRecord(eFork, 0);
        cudaStreamWaitEvent(s2, eFork, 0);
        prep_kernel<<<(EDIM * FFN / 4) / 256, 256, 0, s2>>>(W2);   // side (|| h)
        cudaEventRecord(ePrep, s2);

        h_kernel<<<TOKENS / 32, 256>>>(x, theta, W1, b1);          // main

        cudaStreamWaitEvent(0, ePrep, 0);
        gemm_kernel<<<ggrid, GT, SMEM_TOTAL>>>(b2, out);           // main
    } else {
        // R12 sequential fallback
        prep_kernel<<<(EDIM * FFN / 4) / 256, 256>>>(W2);
        h_kernel<<<TOKENS / 32, 256>>>(x, theta, W1, b1);
        gemm_kernel<<<ggrid, GT, SMEM_TOTAL>>>(b2, out);
    }
}